// round 1
// baseline (speedup 1.0000x reference)
#include <cuda_runtime.h>

#define H 2048
#define S 8192

// Scratch (no allocs allowed)
__device__ float g_u[H];
__device__ float g_energy[S];

// ---------------------------------------------------------------------------
// Kernel 0: zero the u accumulator
// ---------------------------------------------------------------------------
__global__ void k_zero_u() {
    int j = blockIdx.x * blockDim.x + threadIdx.x;
    if (j < H) g_u[j] = 0.0f;
}

// ---------------------------------------------------------------------------
// Kernel 1: u[j] = sum_i h[i] * W[i, j]   (W row-major [H,H])
// Grid: (H/256, ICHUNKS). Each block-y handles H/ICHUNKS rows; partials via
// atomicAdd. Accesses to W are fully coalesced across j.
// ---------------------------------------------------------------------------
#define ICHUNKS 16
#define IROWS   (H / ICHUNKS)  // 128

__global__ void k_compute_u(const float* __restrict__ h,
                            const float* __restrict__ W) {
    int j  = blockIdx.x * blockDim.x + threadIdx.x;   // column
    int i0 = blockIdx.y * IROWS;

    float acc = 0.0f;
#pragma unroll 8
    for (int i = i0; i < i0 + IROWS; ++i) {
        acc = fmaf(h[i], W[(size_t)i * H + j], acc);
    }
    atomicAdd(&g_u[j], acc);
}

// ---------------------------------------------------------------------------
// Kernel 2: energy[s] = enc[s,:] . u   — one warp per row s.
// enc row is 2048 contiguous floats = 512 float4; 16 float4 per lane.
// u (8KB) is re-read by every warp and stays L1/L2 resident.
// ---------------------------------------------------------------------------
__global__ void k_energy(const float* __restrict__ enc) {
    int gwarp = (blockIdx.x * blockDim.x + threadIdx.x) >> 5;
    int lane  = threadIdx.x & 31;
    if (gwarp >= S) return;

    const float4* row = reinterpret_cast<const float4*>(enc + (size_t)gwarp * H);
    const float4* uv  = reinterpret_cast<const float4*>(g_u);

    float acc = 0.0f;
#pragma unroll
    for (int k = 0; k < (H / 4) / 32; ++k) {       // 16 iterations
        float4 v = row[lane + k * 32];
        float4 u = uv[lane + k * 32];
        acc = fmaf(v.x, u.x, acc);
        acc = fmaf(v.y, u.y, acc);
        acc = fmaf(v.z, u.z, acc);
        acc = fmaf(v.w, u.w, acc);
    }
#pragma unroll
    for (int off = 16; off; off >>= 1)
        acc += __shfl_xor_sync(0xFFFFFFFFu, acc, off);

    if (lane == 0) g_energy[gwarp] = acc;
}

// ---------------------------------------------------------------------------
// Kernel 3: softmax over 8192 energies (single block, 1024 threads, 8/thread)
// ---------------------------------------------------------------------------
__global__ void k_softmax(float* __restrict__ out) {
    __shared__ float red[32];
    __shared__ float bmax, bsum;

    const int tid = threadIdx.x;          // 0..1023
    const int lane = tid & 31;
    const int wid  = tid >> 5;

    float vals[8];
    float m = -1e30f;
#pragma unroll
    for (int k = 0; k < 8; ++k) {
        vals[k] = g_energy[tid + k * 1024];
        m = fmaxf(m, vals[k]);
    }
    // block max
#pragma unroll
    for (int off = 16; off; off >>= 1)
        m = fmaxf(m, __shfl_xor_sync(0xFFFFFFFFu, m, off));
    if (lane == 0) red[wid] = m;
    __syncthreads();
    if (tid < 32) {
        float v = red[lane];
#pragma unroll
        for (int off = 16; off; off >>= 1)
            v = fmaxf(v, __shfl_xor_sync(0xFFFFFFFFu, v, off));
        if (lane == 0) bmax = v;
    }
    __syncthreads();
    const float mx = bmax;

    float s = 0.0f;
#pragma unroll
    for (int k = 0; k < 8; ++k) {
        vals[k] = __expf(vals[k] - mx);
        s += vals[k];
    }
#pragma unroll
    for (int off = 16; off; off >>= 1)
        s += __shfl_xor_sync(0xFFFFFFFFu, s, off);
    if (lane == 0) red[wid] = s;
    __syncthreads();
    if (tid < 32) {
        float v = red[lane];
#pragma unroll
        for (int off = 16; off; off >>= 1)
            v += __shfl_xor_sync(0xFFFFFFFFu, v, off);
        if (lane == 0) bsum = v;
    }
    __syncthreads();
    const float inv = 1.0f / bsum;

#pragma unroll
    for (int k = 0; k < 8; ++k)
        out[tid + k * 1024] = vals[k] * inv;
}

// ---------------------------------------------------------------------------
// Launch
// Inputs (metadata order): hidden[2048], encoder_outputs[8192*2048],
//                          W[2048*2048], b[2048] (b is softmax-invariant shift)
// Output: 8192 floats.
// ---------------------------------------------------------------------------
extern "C" void kernel_launch(void* const* d_in, const int* in_sizes, int n_in,
                              void* d_out, int out_size) {
    const float* hidden = (const float*)d_in[0];
    const float* enc    = (const float*)d_in[1];
    const float* W      = (const float*)d_in[2];
    float* out          = (float*)d_out;

    k_zero_u<<<H / 256, 256>>>();

    dim3 g1(H / 256, ICHUNKS);
    k_compute_u<<<g1, 256>>>(hidden, W);

    // S warps, 8 warps per 256-thread block
    k_energy<<<(S * 32) / 256, 256>>>(enc);

    k_softmax<<<1, 1024>>>(out);
}

// round 2
// speedup vs baseline: 1.2429x; 1.2429x over previous
#include <cuda_runtime.h>
#include <math_constants.h>

#define H 2048
#define S 8192

// Scratch (no allocs allowed). g_u starts zero (static init) and every
// invocation re-zeros it at the end of k_norm, so the "g_u == 0 on entry"
// invariant holds on every call (correctness run, capture, every replay).
__device__ float g_u[H];
__device__ float g_energy[S];
__device__ float g_mb[S / 8];     // per-energy-block local max   (1024)
__device__ float g_zb[S / 8];     // per-energy-block exp-sum     (1024)
__device__ float g_M;             // global max
__device__ float g_invZ;          // 1 / global sum

// ---------------------------------------------------------------------------
// Kernel 1: u[j] += sum over an i-chunk of h[i] * W[i, j]   (W row-major)
// Grid (H/256, ICHUNKS) = (8, 32) = 256 blocks. Coalesced on j. atomicAdd
// partials into pre-zeroed g_u.
// ---------------------------------------------------------------------------
#define ICHUNKS 32
#define IROWS   (H / ICHUNKS)     // 64

__global__ void k_compute_u(const float* __restrict__ h,
                            const float* __restrict__ W) {
    int j  = blockIdx.x * blockDim.x + threadIdx.x;
    int i0 = blockIdx.y * IROWS;

    float acc = 0.0f;
#pragma unroll 8
    for (int i = i0; i < i0 + IROWS; ++i) {
        acc = fmaf(h[i], W[(size_t)i * H + j], acc);
    }
    atomicAdd(&g_u[j], acc);
}

// ---------------------------------------------------------------------------
// Kernel 2: energy[s] = enc[s,:] . u  — one warp per row, 8 rows per block.
// Each block also emits (m_b, z_b) = (local max, sum of exp(e - m_b)) so the
// softmax reduction is pre-aggregated 8:1 for free.
// ---------------------------------------------------------------------------
__global__ void k_energy(const float* __restrict__ enc) {
    __shared__ float sE[8];

    int wid  = threadIdx.x >> 5;
    int lane = threadIdx.x & 31;
    int s    = blockIdx.x * 8 + wid;

    const float4* row = reinterpret_cast<const float4*>(enc + (size_t)s * H);
    const float4* uv  = reinterpret_cast<const float4*>(g_u);

    float acc = 0.0f;
#pragma unroll
    for (int k = 0; k < (H / 4) / 32; ++k) {   // 16 iterations
        float4 v = row[lane + k * 32];
        float4 u = uv[lane + k * 32];
        acc = fmaf(v.x, u.x, acc);
        acc = fmaf(v.y, u.y, acc);
        acc = fmaf(v.z, u.z, acc);
        acc = fmaf(v.w, u.w, acc);
    }
#pragma unroll
    for (int off = 16; off; off >>= 1)
        acc += __shfl_xor_sync(0xFFFFFFFFu, acc, off);

    if (lane == 0) {
        g_energy[s] = acc;
        sE[wid] = acc;
    }
    __syncthreads();

    if (threadIdx.x == 0) {
        float m = sE[0];
#pragma unroll
        for (int k = 1; k < 8; ++k) m = fmaxf(m, sE[k]);
        float z = 0.0f;
#pragma unroll
        for (int k = 0; k < 8; ++k) z += __expf(sE[k] - m);
        g_mb[blockIdx.x] = m;
        g_zb[blockIdx.x] = z;
    }
}

// ---------------------------------------------------------------------------
// Kernel 3: combine 1024 (m_b, z_b) pairs into (M, 1/Z). One block, 1024 thr.
// ---------------------------------------------------------------------------
__global__ void k_reduce() {
    __shared__ float red[32];
    __shared__ float sM;

    const int tid  = threadIdx.x;
    const int lane = tid & 31;
    const int wid  = tid >> 5;

    float m = g_mb[tid];
    float z = g_zb[tid];

    // block max
    float mm = m;
#pragma unroll
    for (int off = 16; off; off >>= 1)
        mm = fmaxf(mm, __shfl_xor_sync(0xFFFFFFFFu, mm, off));
    if (lane == 0) red[wid] = mm;
    __syncthreads();
    if (tid < 32) {
        float v = red[lane];
#pragma unroll
        for (int off = 16; off; off >>= 1)
            v = fmaxf(v, __shfl_xor_sync(0xFFFFFFFFu, v, off));
        if (lane == 0) sM = v;
    }
    __syncthreads();
    const float M = sM;

    float y = z * __expf(m - M);
#pragma unroll
    for (int off = 16; off; off >>= 1)
        y += __shfl_xor_sync(0xFFFFFFFFu, y, off);
    if (lane == 0) red[wid] = y;
    __syncthreads();
    if (tid < 32) {
        float v = red[lane];
#pragma unroll
        for (int off = 16; off; off >>= 1)
            v += __shfl_xor_sync(0xFFFFFFFFu, v, off);
        if (lane == 0) {
            g_M    = M;
            g_invZ = 1.0f / v;
        }
    }
}

// ---------------------------------------------------------------------------
// Kernel 4: normalize across 32 blocks (spread exps over SMs), and re-zero
// g_u for the next invocation.
// ---------------------------------------------------------------------------
__global__ void k_norm(float* __restrict__ out) {
    int s = blockIdx.x * blockDim.x + threadIdx.x;   // 0..8191
    float M    = g_M;
    float invZ = g_invZ;
    out[s] = __expf(g_energy[s] - M) * invZ;
    if (s < H) g_u[s] = 0.0f;                        // restore invariant
}

// ---------------------------------------------------------------------------
// Launch. Inputs: hidden[2048], encoder_outputs[8192*2048], W[2048*2048],
// b[2048] (zero + softmax-invariant -> ignored). Output: 8192 floats.
// ---------------------------------------------------------------------------
extern "C" void kernel_launch(void* const* d_in, const int* in_sizes, int n_in,
                              void* d_out, int out_size) {
    const float* hidden = (const float*)d_in[0];
    const float* enc    = (const float*)d_in[1];
    const float* W      = (const float*)d_in[2];
    float* out          = (float*)d_out;

    dim3 g1(H / 256, ICHUNKS);
    k_compute_u<<<g1, 256>>>(hidden, W);

    k_energy<<<S / 8, 256>>>(enc);

    k_reduce<<<1, 1024>>>();

    k_norm<<<S / 256, 256>>>(out);
}